// round 2
// baseline (speedup 1.0000x reference)
#include <cuda_runtime.h>

#define NB 128
#define NN 128
#define INNER 40
#define OUTD 512
#define FCH 41

typedef unsigned long long ull;

// Scratch (allocation-free: device globals)
__device__ float g_S0[NB * NN * INNER];     // row sums over j of g[b,i,j,f], f<40
__device__ float g_core0[NB * NN * INNER];  // diagonal attrs g[b,i,i,f], f<40
__device__ float g_c[NB * NN];              // column sums of bonds: sum_j g[b,j,i,40]

// ---------------- helpers ----------------
__device__ __forceinline__ ull pk(float a, float b) {
    ull r;
    asm("mov.b64 %0, {%1,%2};" : "=l"(r) : "f"(a), "f"(b));
    return r;
}
__device__ __forceinline__ ull fma2(ull a, ull b, ull c) {
    ull d;
    asm("fma.rn.f32x2 %0, %1, %2, %3;" : "=l"(d) : "l"(a), "l"(b), "l"(c));
    return d;
}
__device__ __forceinline__ float lo64(ull v) { return __uint_as_float((unsigned)v); }
__device__ __forceinline__ float hi64(ull v) { return __uint_as_float((unsigned)(v >> 32)); }

__device__ __forceinline__ float wred_max(float v) {
#pragma unroll
    for (int o = 16; o; o >>= 1) v = fmaxf(v, __shfl_xor_sync(0xffffffffu, v, o));
    return v;
}
__device__ __forceinline__ float wred_sum(float v) {
#pragma unroll
    for (int o = 16; o; o >>= 1) v += __shfl_xor_sync(0xffffffffu, v, o);
    return v;
}

// ---------------- kernel 0: init ----------------
__global__ void k_init(float* __restrict__ out) {
    int idx = blockIdx.x * blockDim.x + threadIdx.x;
    if (idx < NB * NN) g_c[idx] = 0.f;
    if (idx < NB * OUTD) out[idx] = 0.f;
}

// ---------------- kernel 1: streaming row reduction ----------------
// One block per (b,i) row: 128*41 contiguous floats. 328 threads = 41 channels x 8 j-lanes;
// tid = l*41 + f maps linearly to address offset (j0+l)*41+f -> fully coalesced.
__global__ void k_rowsum(const float* __restrict__ g) {
    const int row = blockIdx.x;          // b*128 + i
    const int i   = row & (NN - 1);
    const int b   = row >> 7;
    const int t   = threadIdx.x;         // 0..327
    const int f   = t % FCH;
    const int l   = t / FCH;             // 0..7
    const float* base = g + (long long)row * (NN * FCH);

    __shared__ float s[8][FCH];

    float acc = 0.f;
    if (f == FCH - 1) {
        // bonds channel: contributes to transposed column sums c[b, j]
#pragma unroll
        for (int j = l; j < NN; j += 8) {
            atomicAdd(&g_c[b * NN + j], base[j * FCH + f]);
        }
    } else {
        float diag = 0.f;
#pragma unroll
        for (int j = l; j < NN; j += 8) {
            float v = base[j * FCH + f];
            acc += v;
            if (j == i) diag = v;
        }
        if (l == (i & 7)) g_core0[row * INNER + f] = diag;
    }
    s[l][f] = acc;
    __syncthreads();
    if (l == 0 && f < INNER) {
        float tot = 0.f;
#pragma unroll
        for (int q = 0; q < 8; q++) tot += s[q][f];
        g_S0[row * INNER + f] = tot;
    }
}

// ---------------- kernel 2: cores + GEMM + softmax + fp ----------------
// grid (128, 4): batch b, node group of 32. block = 128 threads, thread owns 4 outputs.
__global__ void __launch_bounds__(128) k_compute(
    const float* __restrict__ Wi,   // (3,40,40)
    const float* __restrict__ bi,   // (3,1,40)
    const float* __restrict__ Wo,   // (3,40,512)
    const float* __restrict__ bo,   // (3,1,512)
    float* __restrict__ out)        // (128,512)
{
    const int b   = blockIdx.x;
    const int i0  = blockIdx.y * 32;
    const int tid = threadIdx.x;
    const int warp = tid >> 5, lane = tid & 31;

    __shared__ float shA[32][INNER + 1];   // S0, later pre2 (padded: stride 41 -> conflict-free)
    __shared__ float shC0[32][INNER + 1];  // core0
    __shared__ float shc[32];              // c[i] = colsum + 1
    __shared__ __align__(16) float cores[3][INNER][32];  // [d][f][node]
    __shared__ float redmax[4][8];
    __shared__ float redsum[4][8];

    // stage S0 / core0 / c
    for (int idx = tid; idx < 32 * INNER; idx += 128) {
        int n = idx / INNER, f2 = idx % INNER;
        int row = b * NN + i0 + n;
        shA[n][f2] = g_S0[row * INNER + f2];
        float cv = g_core0[row * INNER + f2];
        shC0[n][f2] = cv;
        cores[0][f2][n] = cv;
    }
    if (tid < 32) shc[tid] = g_c[b * NN + i0 + tid] + 1.0f;
    __syncthreads();

    // nc1 = S0 @ W1 + b1   (idx = f'*32 + n so W value broadcasts across the warp)
    for (int idx = tid; idx < INNER * 32; idx += 128) {
        int fp = idx >> 5, n = idx & 31;
        float s = bi[INNER + fp];
#pragma unroll
        for (int f2 = 0; f2 < INNER; f2++)
            s = fmaf(shA[n][f2], Wi[INNER * INNER + f2 * INNER + fp], s);
        cores[1][fp][n] = s;
    }
    __syncthreads();

    // pre2 = S0 + c * (nc1 - core0), in place over shA
    for (int idx = tid; idx < INNER * 32; idx += 128) {
        int f2 = idx >> 5, n = idx & 31;
        float d1 = cores[1][f2][n] - shC0[n][f2];
        shA[n][f2] = fmaf(shc[n], d1, shA[n][f2]);
    }
    __syncthreads();

    // nc2 = pre2 @ W2 + b2
    for (int idx = tid; idx < INNER * 32; idx += 128) {
        int fp = idx >> 5, n = idx & 31;
        float s = bi[2 * INNER + fp];
#pragma unroll
        for (int f2 = 0; f2 < INNER; f2++)
            s = fmaf(shA[n][f2], Wi[2 * INNER * INNER + f2 * INNER + fp], s);
        cores[2][fp][n] = s;
    }
    __syncthreads();

    // ---- logits GEMM (f32x2) + softmax + fp accumulation ----
    float fp0 = 0.f, fp1 = 0.f, fp2 = 0.f, fp3 = 0.f;

    for (int d = 0; d < 3; d++) {
        const float* Wd = Wo + d * (INNER * OUTD) + (tid << 2);
        float4 bv = *reinterpret_cast<const float4*>(bo + d * OUTD + (tid << 2));
        const ull bb0 = pk(bv.x, bv.x), bb1 = pk(bv.y, bv.y),
                  bb2 = pk(bv.z, bv.z), bb3 = pk(bv.w, bv.w);

        for (int ch = 0; ch < 4; ch++) {   // 8 nodes per chunk (4 f32x2 pairs)
            ull acc[4][4];
#pragma unroll
            for (int p = 0; p < 4; p++) {
                acc[0][p] = bb0; acc[1][p] = bb1; acc[2][p] = bb2; acc[3][p] = bb3;
            }
            const ull* cr = reinterpret_cast<const ull*>(&cores[d][0][ch * 8]);
#pragma unroll 8
            for (int f2 = 0; f2 < INNER; f2++) {
                float4 w4 = *reinterpret_cast<const float4*>(Wd + f2 * OUTD);
                ull w0 = pk(w4.x, w4.x), w1 = pk(w4.y, w4.y),
                    w2 = pk(w4.z, w4.z), w3 = pk(w4.w, w4.w);
                ull c0 = cr[f2 * 16 + 0], c1 = cr[f2 * 16 + 1],
                    c2 = cr[f2 * 16 + 2], c3 = cr[f2 * 16 + 3];
                acc[0][0] = fma2(c0, w0, acc[0][0]);
                acc[1][0] = fma2(c0, w1, acc[1][0]);
                acc[2][0] = fma2(c0, w2, acc[2][0]);
                acc[3][0] = fma2(c0, w3, acc[3][0]);
                acc[0][1] = fma2(c1, w0, acc[0][1]);
                acc[1][1] = fma2(c1, w1, acc[1][1]);
                acc[2][1] = fma2(c1, w2, acc[2][1]);
                acc[3][1] = fma2(c1, w3, acc[3][1]);
                acc[0][2] = fma2(c2, w0, acc[0][2]);
                acc[1][2] = fma2(c2, w1, acc[1][2]);
                acc[2][2] = fma2(c2, w2, acc[2][2]);
                acc[3][2] = fma2(c2, w3, acc[3][2]);
                acc[0][3] = fma2(c3, w0, acc[0][3]);
                acc[1][3] = fma2(c3, w1, acc[1][3]);
                acc[2][3] = fma2(c3, w2, acc[2][3]);
                acc[3][3] = fma2(c3, w3, acc[3][3]);
            }

            // unpack logits: node 2p (lo), node 2p+1 (hi)
            float vl[4][4], vh[4][4];
#pragma unroll
            for (int k = 0; k < 4; k++)
#pragma unroll
                for (int p = 0; p < 4; p++) {
                    vl[k][p] = lo64(acc[k][p]);
                    vh[k][p] = hi64(acc[k][p]);
                }

            // per-node max over 512 outputs (thread-local -> warp -> block)
            float ml[4], mh[4];
#pragma unroll
            for (int p = 0; p < 4; p++) {
                ml[p] = fmaxf(fmaxf(vl[0][p], vl[1][p]), fmaxf(vl[2][p], vl[3][p]));
                mh[p] = fmaxf(fmaxf(vh[0][p], vh[1][p]), fmaxf(vh[2][p], vh[3][p]));
                ml[p] = wred_max(ml[p]);
                mh[p] = wred_max(mh[p]);
            }
            if (lane == 0) {
#pragma unroll
                for (int p = 0; p < 4; p++) {
                    redmax[warp][2 * p]     = ml[p];
                    redmax[warp][2 * p + 1] = mh[p];
                }
            }
            __syncthreads();
            float M[8];
#pragma unroll
            for (int nn = 0; nn < 8; nn++)
                M[nn] = fmaxf(fmaxf(redmax[0][nn], redmax[1][nn]),
                              fmaxf(redmax[2][nn], redmax[3][nn]));

            // exp + per-node sum
            float sl[4], sh2[4];
#pragma unroll
            for (int p = 0; p < 4; p++) {
                float s1 = 0.f, s2 = 0.f;
#pragma unroll
                for (int k = 0; k < 4; k++) {
                    vl[k][p] = __expf(vl[k][p] - M[2 * p]);
                    s1 += vl[k][p];
                    vh[k][p] = __expf(vh[k][p] - M[2 * p + 1]);
                    s2 += vh[k][p];
                }
                sl[p]  = wred_sum(s1);
                sh2[p] = wred_sum(s2);
            }
            if (lane == 0) {
#pragma unroll
                for (int p = 0; p < 4; p++) {
                    redsum[warp][2 * p]     = sl[p];
                    redsum[warp][2 * p + 1] = sh2[p];
                }
            }
            __syncthreads();
            float R[8];
#pragma unroll
            for (int nn = 0; nn < 8; nn++)
                R[nn] = 1.0f / (redsum[0][nn] + redsum[1][nn] +
                                redsum[2][nn] + redsum[3][nn]);

#pragma unroll
            for (int p = 0; p < 4; p++) {
                fp0 += vl[0][p] * R[2 * p] + vh[0][p] * R[2 * p + 1];
                fp1 += vl[1][p] * R[2 * p] + vh[1][p] * R[2 * p + 1];
                fp2 += vl[2][p] * R[2 * p] + vh[2][p] * R[2 * p + 1];
                fp3 += vl[3][p] * R[2 * p] + vh[3][p] * R[2 * p + 1];
            }
        }
    }

    float* po = out + b * OUTD + (tid << 2);
    atomicAdd(po + 0, fp0);
    atomicAdd(po + 1, fp1);
    atomicAdd(po + 2, fp2);
    atomicAdd(po + 3, fp3);
}

// ---------------- launch ----------------
extern "C" void kernel_launch(void* const* d_in, const int* in_sizes, int n_in,
                              void* d_out, int out_size) {
    const float* graph = (const float*)d_in[0];
    const float* Wi    = (const float*)d_in[1];
    const float* bi    = (const float*)d_in[2];
    const float* Wo    = (const float*)d_in[3];
    const float* bo    = (const float*)d_in[4];
    float* out = (float*)d_out;

    k_init<<<(NB * OUTD + 255) / 256, 256>>>(out);
    k_rowsum<<<NB * NN, FCH * 8>>>(graph);
    dim3 g2(NB, 4);
    k_compute<<<g2, 128>>>(Wi, bi, Wo, bo, out);
}

// round 3
// speedup vs baseline: 1.0547x; 1.0547x over previous
#include <cuda_runtime.h>

#define NB 128
#define NN 128
#define INNER 40
#define OUTD 512
#define FCH 41
#define ROWF (NN * FCH)          // 5248 floats per (b,i) row
#define ROWQ (ROWF / 4)          // 1312 float4 per row

typedef unsigned long long ull;

// Scratch (allocation-free: device globals)
__device__ float g_S0[NB * NN * INNER];     // row sums over j of g[b,i,j,f], f<40
__device__ float g_core0[NB * NN * INNER];  // diagonal attrs g[b,i,i,f], f<40
__device__ float g_c[NB * NN];              // column sums of bonds: sum_j g[b,j,i,40]

// ---------------- helpers ----------------
__device__ __forceinline__ ull pk(float a, float b) {
    ull r;
    asm("mov.b64 %0, {%1,%2};" : "=l"(r) : "f"(a), "f"(b));
    return r;
}
__device__ __forceinline__ ull fma2(ull a, ull b, ull c) {
    ull d;
    asm("fma.rn.f32x2 %0, %1, %2, %3;" : "=l"(d) : "l"(a), "l"(b), "l"(c));
    return d;
}
__device__ __forceinline__ float lo64(ull v) { return __uint_as_float((unsigned)v); }
__device__ __forceinline__ float hi64(ull v) { return __uint_as_float((unsigned)(v >> 32)); }

__device__ __forceinline__ float wred_max(float v) {
#pragma unroll
    for (int o = 16; o; o >>= 1) v = fmaxf(v, __shfl_xor_sync(0xffffffffu, v, o));
    return v;
}
__device__ __forceinline__ float wred_sum(float v) {
#pragma unroll
    for (int o = 16; o; o >>= 1) v += __shfl_xor_sync(0xffffffffu, v, o);
    return v;
}

// ---------------- kernel 0: init ----------------
__global__ void k_init(float* __restrict__ out) {
    int idx = blockIdx.x * blockDim.x + threadIdx.x;
    if (idx < NB * NN) g_c[idx] = 0.f;
    if (idx < NB * OUTD) out[idx] = 0.f;
}

// ---------------- kernel 1: streaming row reduction (float4 edition) ----------------
// One block per (b,i) row: 1312 float4 = 328 threads x 4 loads.
// Key identity: 4*328 = 1312 = 32*41, so for thread t loading float4 index t+328s,
// element k has channel f_k = (4t+k) % 41 CONSTANT in s, and j = (4t+k)/41 + 32s.
__global__ void __launch_bounds__(FCH * 8) k_rowsum(const float* __restrict__ g) {
    const int row = blockIdx.x;          // b*128 + i
    const int i   = row & (NN - 1);
    const int b   = row >> 7;
    const int t   = threadIdx.x;         // 0..327
    const float4* base = reinterpret_cast<const float4*>(g + (long long)row * ROWF);

    __shared__ float s_flat[ROWF / 4 * 4];   // 1312 floats: per-(t,k) channel partials

    int f4[4], jb[4];
#pragma unroll
    for (int k = 0; k < 4; k++) {
        int e = 4 * t + k;
        f4[k] = e % FCH;
        jb[k] = e / FCH;
    }

    float acc0 = 0.f, acc1 = 0.f, acc2 = 0.f, acc3 = 0.f;

#pragma unroll
    for (int s = 0; s < 4; s++) {
        float4 v4 = base[t + 328 * s];
        const int j0 = 32 * s;
        // k = 0
        if (f4[0] == FCH - 1) atomicAdd(&g_c[b * NN + jb[0] + j0], v4.x);
        else { acc0 += v4.x; if (jb[0] + j0 == i) g_core0[row * INNER + f4[0]] = v4.x; }
        // k = 1
        if (f4[1] == FCH - 1) atomicAdd(&g_c[b * NN + jb[1] + j0], v4.y);
        else { acc1 += v4.y; if (jb[1] + j0 == i) g_core0[row * INNER + f4[1]] = v4.y; }
        // k = 2
        if (f4[2] == FCH - 1) atomicAdd(&g_c[b * NN + jb[2] + j0], v4.z);
        else { acc2 += v4.z; if (jb[2] + j0 == i) g_core0[row * INNER + f4[2]] = v4.z; }
        // k = 3
        if (f4[3] == FCH - 1) atomicAdd(&g_c[b * NN + jb[3] + j0], v4.w);
        else { acc3 += v4.w; if (jb[3] + j0 == i) g_core0[row * INNER + f4[3]] = v4.w; }
    }

    // store per-thread partials (float4, conflict-free), then strided channel reduce
    *reinterpret_cast<float4*>(&s_flat[4 * t]) = make_float4(acc0, acc1, acc2, acc3);
    __syncthreads();

    if (t < INNER) {
        float tot = 0.f;
#pragma unroll
        for (int m = 0; m < 32; m++)       // stride 41: 41m mod 32 = 9m, gcd(9,32)=1 -> no conflicts
            tot += s_flat[t + FCH * m];
        g_S0[row * INNER + t] = tot;
    }
}

// ---------------- kernel 2: cores + GEMM + softmax + fp ----------------
// grid (128, 4): batch b, node group of 32. block = 128 threads, thread owns 4 outputs.
__global__ void __launch_bounds__(128) k_compute(
    const float* __restrict__ Wi,   // (3,40,40)
    const float* __restrict__ bi,   // (3,1,40)
    const float* __restrict__ Wo,   // (3,40,512)
    const float* __restrict__ bo,   // (3,1,512)
    float* __restrict__ out)        // (128,512)
{
    const int b   = blockIdx.x;
    const int i0  = blockIdx.y * 32;
    const int tid = threadIdx.x;
    const int warp = tid >> 5, lane = tid & 31;

    __shared__ float shA[32][INNER + 1];   // S0, later pre2 (padded: stride 41 -> conflict-free)
    __shared__ float shC0[32][INNER + 1];  // core0
    __shared__ float shc[32];              // c[i] = colsum + 1
    __shared__ __align__(16) float cores[3][INNER][32];  // [d][f][node]
    __shared__ float redmax[4][8];
    __shared__ float redsum[4][8];

    // stage S0 / core0 / c
    for (int idx = tid; idx < 32 * INNER; idx += 128) {
        int n = idx / INNER, f2 = idx % INNER;
        int row = b * NN + i0 + n;
        shA[n][f2] = g_S0[row * INNER + f2];
        float cv = g_core0[row * INNER + f2];
        shC0[n][f2] = cv;
        cores[0][f2][n] = cv;
    }
    if (tid < 32) shc[tid] = g_c[b * NN + i0 + tid] + 1.0f;
    __syncthreads();

    // nc1 = S0 @ W1 + b1   (idx = f'*32 + n so W value broadcasts across the warp)
    for (int idx = tid; idx < INNER * 32; idx += 128) {
        int fp = idx >> 5, n = idx & 31;
        float s = bi[INNER + fp];
#pragma unroll
        for (int f2 = 0; f2 < INNER; f2++)
            s = fmaf(shA[n][f2], Wi[INNER * INNER + f2 * INNER + fp], s);
        cores[1][fp][n] = s;
    }
    __syncthreads();

    // pre2 = S0 + c * (nc1 - core0), in place over shA
    for (int idx = tid; idx < INNER * 32; idx += 128) {
        int f2 = idx >> 5, n = idx & 31;
        float d1 = cores[1][f2][n] - shC0[n][f2];
        shA[n][f2] = fmaf(shc[n], d1, shA[n][f2]);
    }
    __syncthreads();

    // nc2 = pre2 @ W2 + b2
    for (int idx = tid; idx < INNER * 32; idx += 128) {
        int fp = idx >> 5, n = idx & 31;
        float s = bi[2 * INNER + fp];
#pragma unroll
        for (int f2 = 0; f2 < INNER; f2++)
            s = fmaf(shA[n][f2], Wi[2 * INNER * INNER + f2 * INNER + fp], s);
        cores[2][fp][n] = s;
    }
    __syncthreads();

    // ---- logits GEMM (f32x2) + softmax + fp accumulation ----
    float fp0 = 0.f, fp1 = 0.f, fp2 = 0.f, fp3 = 0.f;

    for (int d = 0; d < 3; d++) {
        const float* Wd = Wo + d * (INNER * OUTD) + (tid << 2);
        float4 bv = *reinterpret_cast<const float4*>(bo + d * OUTD + (tid << 2));
        const ull bb0 = pk(bv.x, bv.x), bb1 = pk(bv.y, bv.y),
                  bb2 = pk(bv.z, bv.z), bb3 = pk(bv.w, bv.w);

        for (int ch = 0; ch < 4; ch++) {   // 8 nodes per chunk (4 f32x2 pairs)
            ull acc[4][4];
#pragma unroll
            for (int p = 0; p < 4; p++) {
                acc[0][p] = bb0; acc[1][p] = bb1; acc[2][p] = bb2; acc[3][p] = bb3;
            }
            const ull* cr = reinterpret_cast<const ull*>(&cores[d][0][ch * 8]);
#pragma unroll 8
            for (int f2 = 0; f2 < INNER; f2++) {
                float4 w4 = *reinterpret_cast<const float4*>(Wd + f2 * OUTD);
                ull w0 = pk(w4.x, w4.x), w1 = pk(w4.y, w4.y),
                    w2 = pk(w4.z, w4.z), w3 = pk(w4.w, w4.w);
                ull c0 = cr[f2 * 16 + 0], c1 = cr[f2 * 16 + 1],
                    c2 = cr[f2 * 16 + 2], c3 = cr[f2 * 16 + 3];
                acc[0][0] = fma2(c0, w0, acc[0][0]);
                acc[1][0] = fma2(c0, w1, acc[1][0]);
                acc[2][0] = fma2(c0, w2, acc[2][0]);
                acc[3][0] = fma2(c0, w3, acc[3][0]);
                acc[0][1] = fma2(c1, w0, acc[0][1]);
                acc[1][1] = fma2(c1, w1, acc[1][1]);
                acc[2][1] = fma2(c1, w2, acc[2][1]);
                acc[3][1] = fma2(c1, w3, acc[3][1]);
                acc[0][2] = fma2(c2, w0, acc[0][2]);
                acc[1][2] = fma2(c2, w1, acc[1][2]);
                acc[2][2] = fma2(c2, w2, acc[2][2]);
                acc[3][2] = fma2(c2, w3, acc[3][2]);
                acc[0][3] = fma2(c3, w0, acc[0][3]);
                acc[1][3] = fma2(c3, w1, acc[1][3]);
                acc[2][3] = fma2(c3, w2, acc[2][3]);
                acc[3][3] = fma2(c3, w3, acc[3][3]);
            }

            // unpack logits: node 2p (lo), node 2p+1 (hi)
            float vl[4][4], vh[4][4];
#pragma unroll
            for (int k = 0; k < 4; k++)
#pragma unroll
                for (int p = 0; p < 4; p++) {
                    vl[k][p] = lo64(acc[k][p]);
                    vh[k][p] = hi64(acc[k][p]);
                }

            // per-node max over 512 outputs (thread-local -> warp -> block)
            float ml[4], mh[4];
#pragma unroll
            for (int p = 0; p < 4; p++) {
                ml[p] = fmaxf(fmaxf(vl[0][p], vl[1][p]), fmaxf(vl[2][p], vl[3][p]));
                mh[p] = fmaxf(fmaxf(vh[0][p], vh[1][p]), fmaxf(vh[2][p], vh[3][p]));
                ml[p] = wred_max(ml[p]);
                mh[p] = wred_max(mh[p]);
            }
            if (lane == 0) {
#pragma unroll
                for (int p = 0; p < 4; p++) {
                    redmax[warp][2 * p]     = ml[p];
                    redmax[warp][2 * p + 1] = mh[p];
                }
            }
            __syncthreads();
            float M[8];
#pragma unroll
            for (int nn = 0; nn < 8; nn++)
                M[nn] = fmaxf(fmaxf(redmax[0][nn], redmax[1][nn]),
                              fmaxf(redmax[2][nn], redmax[3][nn]));

            // exp + per-node sum
            float sl[4], sh2[4];
#pragma unroll
            for (int p = 0; p < 4; p++) {
                float s1 = 0.f, s2 = 0.f;
#pragma unroll
                for (int k = 0; k < 4; k++) {
                    vl[k][p] = __expf(vl[k][p] - M[2 * p]);
                    s1 += vl[k][p];
                    vh[k][p] = __expf(vh[k][p] - M[2 * p + 1]);
                    s2 += vh[k][p];
                }
                sl[p]  = wred_sum(s1);
                sh2[p] = wred_sum(s2);
            }
            if (lane == 0) {
#pragma unroll
                for (int p = 0; p < 4; p++) {
                    redsum[warp][2 * p]     = sl[p];
                    redsum[warp][2 * p + 1] = sh2[p];
                }
            }
            __syncthreads();
            float R[8];
#pragma unroll
            for (int nn = 0; nn < 8; nn++)
                R[nn] = 1.0f / (redsum[0][nn] + redsum[1][nn] +
                                redsum[2][nn] + redsum[3][nn]);

#pragma unroll
            for (int p = 0; p < 4; p++) {
                fp0 += vl[0][p] * R[2 * p] + vh[0][p] * R[2 * p + 1];
                fp1 += vl[1][p] * R[2 * p] + vh[1][p] * R[2 * p + 1];
                fp2 += vl[2][p] * R[2 * p] + vh[2][p] * R[2 * p + 1];
                fp3 += vl[3][p] * R[2 * p] + vh[3][p] * R[2 * p + 1];
            }
        }
    }

    float* po = out + b * OUTD + (tid << 2);
    atomicAdd(po + 0, fp0);
    atomicAdd(po + 1, fp1);
    atomicAdd(po + 2, fp2);
    atomicAdd(po + 3, fp3);
}

// ---------------- launch ----------------
extern "C" void kernel_launch(void* const* d_in, const int* in_sizes, int n_in,
                              void* d_out, int out_size) {
    const float* graph = (const float*)d_in[0];
    const float* Wi    = (const float*)d_in[1];
    const float* bi    = (const float*)d_in[2];
    const float* Wo    = (const float*)d_in[3];
    const float* bo    = (const float*)d_in[4];
    float* out = (float*)d_out;

    k_init<<<(NB * OUTD + 255) / 256, 256>>>(out);
    k_rowsum<<<NB * NN, FCH * 8>>>(graph);
    dim3 g2(NB, 4);
    k_compute<<<g2, 128>>>(Wi, bi, Wo, bo, out);
}

// round 4
// speedup vs baseline: 1.9126x; 1.8135x over previous
#include <cuda_runtime.h>

#define NB 128
#define NN 128
#define INNER 40
#define OUTD 512
#define FCH 41
#define ROWF (NN * FCH)          // 5248 floats per (b,i) row

typedef unsigned long long ull;

// Scratch (allocation-free: device globals)
__device__ float g_S0[NB * NN * INNER];     // row sums over j of g[b,i,j,f], f<40
__device__ float g_core0[NB * NN * INNER];  // diagonal attrs g[b,i,i,f], f<40
__device__ float g_bonds[NB * NN * NN];     // g[b,i,j,40] laid out [b][i][j]

// ---------------- helpers ----------------
__device__ __forceinline__ ull pk(float a, float b) {
    ull r;
    asm("mov.b64 %0, {%1,%2};" : "=l"(r) : "f"(a), "f"(b));
    return r;
}
__device__ __forceinline__ ull fma2(ull a, ull b, ull c) {
    ull d;
    asm("fma.rn.f32x2 %0, %1, %2, %3;" : "=l"(d) : "l"(a), "l"(b), "l"(c));
    return d;
}
__device__ __forceinline__ float lo64(ull v) { return __uint_as_float((unsigned)v); }
__device__ __forceinline__ float hi64(ull v) { return __uint_as_float((unsigned)(v >> 32)); }

__device__ __forceinline__ float wred_max(float v) {
#pragma unroll
    for (int o = 16; o; o >>= 1) v = fmaxf(v, __shfl_xor_sync(0xffffffffu, v, o));
    return v;
}
__device__ __forceinline__ float wred_sum(float v) {
#pragma unroll
    for (int o = 16; o; o >>= 1) v += __shfl_xor_sync(0xffffffffu, v, o);
    return v;
}

// ---------------- kernel 1: streaming row reduction ----------------
// One block per (b,i) row: 1312 float4 = 328 threads x 4 loads.
// 4*328 = 1312 = 32*41, so for thread t loading float4 index t+328s,
// element k has channel f_k = (4t+k) % 41 CONSTANT in s, and j = (4t+k)/41 + 32s.
// No atomics: bonds row is stored verbatim to g_bonds; out is zeroed here
// (16384 blocks <-> 16384 float4 of out).
__global__ void __launch_bounds__(FCH * 8) k_rowsum(const float* __restrict__ g,
                                                    float* __restrict__ out) {
    const int row = blockIdx.x;          // b*128 + i
    const int i   = row & (NN - 1);
    const int t   = threadIdx.x;         // 0..327
    const float4* base = reinterpret_cast<const float4*>(g + (long long)row * ROWF);

    __shared__ float s_flat[FCH * 8 * 4];   // 1312 floats: per-(t,k) channel partials

    if (t == 0) reinterpret_cast<float4*>(out)[row] = make_float4(0.f, 0.f, 0.f, 0.f);

    int f4[4], jb[4];
#pragma unroll
    for (int k = 0; k < 4; k++) {
        int e = 4 * t + k;
        f4[k] = e % FCH;
        jb[k] = e / FCH;
    }

    float acc0 = 0.f, acc1 = 0.f, acc2 = 0.f, acc3 = 0.f;
    float* brow = g_bonds + row * NN;

#pragma unroll
    for (int s = 0; s < 4; s++) {
        float4 v4 = base[t + 328 * s];
        const int j0 = 32 * s;
        if (f4[0] == FCH - 1) brow[jb[0] + j0] = v4.x;
        else { acc0 += v4.x; if (jb[0] + j0 == i) g_core0[row * INNER + f4[0]] = v4.x; }
        if (f4[1] == FCH - 1) brow[jb[1] + j0] = v4.y;
        else { acc1 += v4.y; if (jb[1] + j0 == i) g_core0[row * INNER + f4[1]] = v4.y; }
        if (f4[2] == FCH - 1) brow[jb[2] + j0] = v4.z;
        else { acc2 += v4.z; if (jb[2] + j0 == i) g_core0[row * INNER + f4[2]] = v4.z; }
        if (f4[3] == FCH - 1) brow[jb[3] + j0] = v4.w;
        else { acc3 += v4.w; if (jb[3] + j0 == i) g_core0[row * INNER + f4[3]] = v4.w; }
    }

    *reinterpret_cast<float4*>(&s_flat[4 * t]) = make_float4(acc0, acc1, acc2, acc3);
    __syncthreads();

    if (t < INNER) {
        float tot = 0.f;
#pragma unroll
        for (int m = 0; m < 32; m++)       // stride 41 mod 32 = 9, gcd(9,32)=1 -> conflict-free
            tot += s_flat[t + FCH * m];
        g_S0[row * INNER + t] = tot;
    }
}

// ---------------- kernel 2: cores + GEMM + softmax + fp ----------------
// grid (128, 4): batch b, node group of 32. block = 128 threads, thread owns 4 outputs.
__global__ void __launch_bounds__(128) k_compute(
    const float* __restrict__ Wi,   // (3,40,40)
    const float* __restrict__ bi,   // (3,1,40)
    const float* __restrict__ Wo,   // (3,40,512)
    const float* __restrict__ bo,   // (3,1,512)
    float* __restrict__ out)        // (128,512)
{
    const int b   = blockIdx.x;
    const int i0  = blockIdx.y * 32;
    const int tid = threadIdx.x;
    const int warp = tid >> 5, lane = tid & 31;

    __shared__ float shA[32][INNER + 1];   // S0, later pre2 (stride 41 -> conflict-free)
    __shared__ float shC0[32][INNER + 1];  // core0
    __shared__ float shc[32];              // c[i] = colsum(bonds) + 1
    __shared__ float shcp[4][32];          // column-sum partials
    __shared__ __align__(16) float cores[3][INNER][32];  // [d][f][node]
    __shared__ float redmax[4][8];
    __shared__ float redsum[4][8];

    // stage S0 / core0
    for (int idx = tid; idx < 32 * INNER; idx += 128) {
        int n = idx / INNER, f2 = idx % INNER;
        int row = b * NN + i0 + n;
        shA[n][f2] = g_S0[row * INNER + f2];
        float cv = g_core0[row * INNER + f2];
        shC0[n][f2] = cv;
        cores[0][f2][n] = cv;
    }
    // column sums of bonds for our 32 nodes: c[i] = sum_j g_bonds[b][j][i]
    {
        const float* bb = g_bonds + (b * NN) * NN + i0 + lane;
        float cp = 0.f;
#pragma unroll 8
        for (int m = 0; m < 32; m++)
            cp += bb[(warp + 4 * m) * NN];
        shcp[warp][lane] = cp;
    }
    __syncthreads();
    if (tid < 32)
        shc[tid] = 1.0f + shcp[0][tid] + shcp[1][tid] + shcp[2][tid] + shcp[3][tid];
    __syncthreads();

    // nc1 = S0 @ W1 + b1   (idx = f'*32 + n so W value broadcasts across the warp)
    for (int idx = tid; idx < INNER * 32; idx += 128) {
        int fp = idx >> 5, n = idx & 31;
        float s = bi[INNER + fp];
#pragma unroll
        for (int f2 = 0; f2 < INNER; f2++)
            s = fmaf(shA[n][f2], Wi[INNER * INNER + f2 * INNER + fp], s);
        cores[1][fp][n] = s;
    }
    __syncthreads();

    // pre2 = S0 + c * (nc1 - core0), in place over shA
    for (int idx = tid; idx < INNER * 32; idx += 128) {
        int f2 = idx >> 5, n = idx & 31;
        float d1 = cores[1][f2][n] - shC0[n][f2];
        shA[n][f2] = fmaf(shc[n], d1, shA[n][f2]);
    }
    __syncthreads();

    // nc2 = pre2 @ W2 + b2
    for (int idx = tid; idx < INNER * 32; idx += 128) {
        int fp = idx >> 5, n = idx & 31;
        float s = bi[2 * INNER + fp];
#pragma unroll
        for (int f2 = 0; f2 < INNER; f2++)
            s = fmaf(shA[n][f2], Wi[2 * INNER * INNER + f2 * INNER + fp], s);
        cores[2][fp][n] = s;
    }
    __syncthreads();

    // ---- logits GEMM (f32x2) + softmax + fp accumulation ----
    float fp0 = 0.f, fp1 = 0.f, fp2 = 0.f, fp3 = 0.f;

    for (int d = 0; d < 3; d++) {
        const float* Wd = Wo + d * (INNER * OUTD) + (tid << 2);
        float4 bv = *reinterpret_cast<const float4*>(bo + d * OUTD + (tid << 2));
        const ull bb0 = pk(bv.x, bv.x), bb1 = pk(bv.y, bv.y),
                  bb2 = pk(bv.z, bv.z), bb3 = pk(bv.w, bv.w);

        for (int ch = 0; ch < 4; ch++) {   // 8 nodes per chunk (4 f32x2 pairs)
            ull acc[4][4];
#pragma unroll
            for (int p = 0; p < 4; p++) {
                acc[0][p] = bb0; acc[1][p] = bb1; acc[2][p] = bb2; acc[3][p] = bb3;
            }
            const ull* cr = reinterpret_cast<const ull*>(&cores[d][0][ch * 8]);
#pragma unroll 8
            for (int f2 = 0; f2 < INNER; f2++) {
                float4 w4 = *reinterpret_cast<const float4*>(Wd + f2 * OUTD);
                ull w0 = pk(w4.x, w4.x), w1 = pk(w4.y, w4.y),
                    w2 = pk(w4.z, w4.z), w3 = pk(w4.w, w4.w);
                ull c0 = cr[f2 * 16 + 0], c1 = cr[f2 * 16 + 1],
                    c2 = cr[f2 * 16 + 2], c3 = cr[f2 * 16 + 3];
                acc[0][0] = fma2(c0, w0, acc[0][0]);
                acc[1][0] = fma2(c0, w1, acc[1][0]);
                acc[2][0] = fma2(c0, w2, acc[2][0]);
                acc[3][0] = fma2(c0, w3, acc[3][0]);
                acc[0][1] = fma2(c1, w0, acc[0][1]);
                acc[1][1] = fma2(c1, w1, acc[1][1]);
                acc[2][1] = fma2(c1, w2, acc[2][1]);
                acc[3][1] = fma2(c1, w3, acc[3][1]);
                acc[0][2] = fma2(c2, w0, acc[0][2]);
                acc[1][2] = fma2(c2, w1, acc[1][2]);
                acc[2][2] = fma2(c2, w2, acc[2][2]);
                acc[3][2] = fma2(c2, w3, acc[3][2]);
                acc[0][3] = fma2(c3, w0, acc[0][3]);
                acc[1][3] = fma2(c3, w1, acc[1][3]);
                acc[2][3] = fma2(c3, w2, acc[2][3]);
                acc[3][3] = fma2(c3, w3, acc[3][3]);
            }

            float vl[4][4], vh[4][4];
#pragma unroll
            for (int k = 0; k < 4; k++)
#pragma unroll
                for (int p = 0; p < 4; p++) {
                    vl[k][p] = lo64(acc[k][p]);
                    vh[k][p] = hi64(acc[k][p]);
                }

            float ml[4], mh[4];
#pragma unroll
            for (int p = 0; p < 4; p++) {
                ml[p] = fmaxf(fmaxf(vl[0][p], vl[1][p]), fmaxf(vl[2][p], vl[3][p]));
                mh[p] = fmaxf(fmaxf(vh[0][p], vh[1][p]), fmaxf(vh[2][p], vh[3][p]));
                ml[p] = wred_max(ml[p]);
                mh[p] = wred_max(mh[p]);
            }
            if (lane == 0) {
#pragma unroll
                for (int p = 0; p < 4; p++) {
                    redmax[warp][2 * p]     = ml[p];
                    redmax[warp][2 * p + 1] = mh[p];
                }
            }
            __syncthreads();
            float M[8];
#pragma unroll
            for (int nn = 0; nn < 8; nn++)
                M[nn] = fmaxf(fmaxf(redmax[0][nn], redmax[1][nn]),
                              fmaxf(redmax[2][nn], redmax[3][nn]));

            float sl[4], sh2[4];
#pragma unroll
            for (int p = 0; p < 4; p++) {
                float s1 = 0.f, s2 = 0.f;
#pragma unroll
                for (int k = 0; k < 4; k++) {
                    vl[k][p] = __expf(vl[k][p] - M[2 * p]);
                    s1 += vl[k][p];
                    vh[k][p] = __expf(vh[k][p] - M[2 * p + 1]);
                    s2 += vh[k][p];
                }
                sl[p]  = wred_sum(s1);
                sh2[p] = wred_sum(s2);
            }
            if (lane == 0) {
#pragma unroll
                for (int p = 0; p < 4; p++) {
                    redsum[warp][2 * p]     = sl[p];
                    redsum[warp][2 * p + 1] = sh2[p];
                }
            }
            __syncthreads();
            float R[8];
#pragma unroll
            for (int nn = 0; nn < 8; nn++)
                R[nn] = 1.0f / (redsum[0][nn] + redsum[1][nn] +
                                redsum[2][nn] + redsum[3][nn]);

#pragma unroll
            for (int p = 0; p < 4; p++) {
                fp0 += vl[0][p] * R[2 * p] + vh[0][p] * R[2 * p + 1];
                fp1 += vl[1][p] * R[2 * p] + vh[1][p] * R[2 * p + 1];
                fp2 += vl[2][p] * R[2 * p] + vh[2][p] * R[2 * p + 1];
                fp3 += vl[3][p] * R[2 * p] + vh[3][p] * R[2 * p + 1];
            }
        }
    }

    float* po = out + b * OUTD + (tid << 2);
    atomicAdd(po + 0, fp0);
    atomicAdd(po + 1, fp1);
    atomicAdd(po + 2, fp2);
    atomicAdd(po + 3, fp3);
}

// ---------------- launch ----------------
extern "C" void kernel_launch(void* const* d_in, const int* in_sizes, int n_in,
                              void* d_out, int out_size) {
    const float* graph = (const float*)d_in[0];
    const float* Wi    = (const float*)d_in[1];
    const float* bi    = (const float*)d_in[2];
    const float* Wo    = (const float*)d_in[3];
    const float* bo    = (const float*)d_in[4];
    float* out = (float*)d_out;

    k_rowsum<<<NB * NN, FCH * 8>>>(graph, out);
    dim3 g2(NB, 4);
    k_compute<<<g2, 128>>>(Wi, bi, Wo, bo, out);
}